// round 2
// baseline (speedup 1.0000x reference)
#include <cuda_runtime.h>

// RotationPerturbationLayer: the reference's dense [B,N,N] tent-weight matmul
// is exactly zero-padded bilinear resampling under rotation (tent kernel has
// support width 2 -> only the 2x2 neighboring taps are nonzero).
//
// theta: [B=4] degrees, image: [C=3, H=80, W=80] fp32
// out:   [B, C, H, W] fp32
//
// One thread per (b, y, x) site; emits all 3 channels to amortize the
// rotation math. Tiny kernel; launch-overhead bound.

#define H 80
#define W 80
#define C 3
#define B 4
#define NPIX (H * W)

__global__ __launch_bounds__(256)
void rot_bilinear_kernel(const float* __restrict__ theta,
                         const float* __restrict__ image,
                         float* __restrict__ out) {
    int idx = blockIdx.x * blockDim.x + threadIdx.x;  // over B * NPIX
    if (idx >= B * NPIX) return;

    int b   = idx / NPIX;
    int pix = idx - b * NPIX;
    int y   = pix / W;
    int x   = pix - y * W;

    const float cx = (W - 1) * 0.5f;   // 39.5
    const float cy = (H - 1) * 0.5f;

    // deg -> rad
    float th = theta[b] * 0.017453292519943295f;
    float s, c;
    __sincosf(th, &s, &c);
    // __sincosf is the fast intrinsic; accuracy ~2 ulp over this range,
    // well inside the 1e-3 rel-err budget. (If it ever fails, swap to sincosf.)

    float x_rel = (float)x - cx;
    float y_rel = (float)y - cy;

    // rotation matrix [[cos, sin], [-sin, cos]]
    float src_x = fmaf(c, x_rel, fmaf(s,  y_rel, cx));
    float src_y = fmaf(-s, x_rel, fmaf(c, y_rel, cy));

    float fx0 = floorf(src_x);
    float fy0 = floorf(src_y);
    int x0 = (int)fx0;
    int y0 = (int)fy0;
    int x1 = x0 + 1;
    int y1 = y0 + 1;
    float ax = src_x - fx0;          // frac in [0,1)
    float ay = src_y - fy0;

    // tent weights: (1-ax) at x0, ax at x1  (same as max(0,1-|src_x - xs|))
    float w00 = (1.0f - ax) * (1.0f - ay);
    float w10 = ax * (1.0f - ay);
    float w01 = (1.0f - ax) * ay;
    float w11 = ax * ay;

    bool x0ok = (x0 >= 0) & (x0 < W);
    bool x1ok = (x1 >= 0) & (x1 < W);
    bool y0ok = (y0 >= 0) & (y0 < H);
    bool y1ok = (y1 >= 0) & (y1 < H);

    // zero-padding: drop taps outside the image
    float m00 = (x0ok & y0ok) ? w00 : 0.0f;
    float m10 = (x1ok & y0ok) ? w10 : 0.0f;
    float m01 = (x0ok & y1ok) ? w01 : 0.0f;
    float m11 = (x1ok & y1ok) ? w11 : 0.0f;

    // clamp indices so addresses are always valid (weight already zeroed)
    int xc0 = min(max(x0, 0), W - 1);
    int xc1 = min(max(x1, 0), W - 1);
    int yc0 = min(max(y0, 0), H - 1);
    int yc1 = min(max(y1, 0), H - 1);

    int i00 = yc0 * W + xc0;
    int i10 = yc0 * W + xc1;
    int i01 = yc1 * W + xc0;
    int i11 = yc1 * W + xc1;

    float* ob = out + (size_t)b * C * NPIX + pix;
    const float* img = image;

    #pragma unroll
    for (int ch = 0; ch < C; ch++) {
        const float* ic = img + ch * NPIX;
        float v = m00 * __ldg(ic + i00);
        v = fmaf(m10, __ldg(ic + i10), v);
        v = fmaf(m01, __ldg(ic + i01), v);
        v = fmaf(m11, __ldg(ic + i11), v);
        ob[ch * NPIX] = v;
    }
}

extern "C" void kernel_launch(void* const* d_in, const int* in_sizes, int n_in,
                              void* d_out, int out_size) {
    // metadata order: theta [4], image [19200] — guard by size anyway
    const float* theta = (const float*)d_in[0];
    const float* image = (const float*)d_in[1];
    if (n_in >= 2 && in_sizes[0] != 4 && in_sizes[1] == 4) {
        theta = (const float*)d_in[1];
        image = (const float*)d_in[0];
    }
    float* out = (float*)d_out;

    int total = B * NPIX;  // 25600 threads
    int threads = 256;
    int blocks = (total + threads - 1) / threads;
    rot_bilinear_kernel<<<blocks, threads>>>(theta, image, out);
}